// round 1
// baseline (speedup 1.0000x reference)
#include <cuda_runtime.h>
#include <cstdint>

#define MARGIN 0.2f
#define NEG_BIG (-3.0e38f)

// Scratch score matrices (B=128 max). No device allocation allowed -> device globals.
__device__ float g_s1[128 * 128];
__device__ float g_s2[128 * 128];

// ---------------------------------------------------------------------------
// score_kernel<O, W, TO, AROW, BROW, SLOT>
// One CTA per (image i = blockIdx.y, caption c = blockIdx.x).
//   out[i*B + c] = sum_w max_{o < img_l[i]} <img[i,o,:], cap[c,w,:]>  / cap_l[c]
// A and B tiles are staged in SMEM *k-major* (transposed) so the FMA loop
// reads one float4 of O-values and one float4 of W-values per k: conflict-free
// broadcast-friendly LDS, 16 (or 8) FFMA per 2 LDS.128.
// ---------------------------------------------------------------------------
template<int O, int W, int TO, int AROW, int BROW, int SLOT>
__global__ __launch_bounds__(128, 1)
void score_kernel(const float* __restrict__ img,
                  const int*   __restrict__ img_l,
                  const float* __restrict__ cap,
                  const int*   __restrict__ cap_l,
                  int B)
{
    constexpr int D  = 128;
    constexpr int OT = (O + TO - 1) / TO;     // tiles along objects
    constexpr int WT = (W + 3) / 4;           // tiles along words (4 wide)
    constexpr int WP = WT * 4;

    __shared__ __align__(16) float AsT[D * AROW];   // [k][o]
    __shared__ __align__(16) float BsT[D * BROW];   // [k][w]
    __shared__ float pm[OT][WP];                    // per-(otile, w) masked max
    __shared__ float wsum[WP];

    const int i   = blockIdx.y;
    const int c   = blockIdx.x;
    const int tid = threadIdx.x;

    const float* __restrict__ Ag = img + (size_t)i * O * D;
    const float* __restrict__ Bg = cap + (size_t)c * W * D;

    // ---- Stage tiles transposed into SMEM (coalesced LDG.32, <=4-way STS) ----
    #pragma unroll 4
    for (int idx = tid; idx < O * D; idx += 128) {
        int o = idx >> 7, k = idx & 127;
        AsT[k * AROW + o] = Ag[idx];
    }
    #pragma unroll 4
    for (int idx = tid; idx < W * D; idx += 128) {
        int w = idx >> 7, k = idx & 127;
        BsT[k * BROW + w] = Bg[idx];
    }
    __syncthreads();

    // ---- Register-tiled dot products: TO x 4 outputs per thread ----
    if (tid < OT * WT) {
        const int to = tid / WT;
        const int tw = tid % WT;

        float acc[TO][4];
        #pragma unroll
        for (int oi = 0; oi < TO; oi++)
            #pragma unroll
            for (int wi = 0; wi < 4; wi++) acc[oi][wi] = 0.0f;

        const float* ap = AsT + to * TO;
        const float* bp = BsT + tw * 4;

        #pragma unroll 4
        for (int k = 0; k < D; k++) {
            float av[TO];
            if constexpr (TO == 4) {
                float4 t = *reinterpret_cast<const float4*>(ap + k * AROW);
                av[0] = t.x; av[1] = t.y; av[2] = t.z; av[3] = t.w;
            } else {
                float2 t = *reinterpret_cast<const float2*>(ap + k * AROW);
                av[0] = t.x; av[1] = t.y;
            }
            float4 bv = *reinterpret_cast<const float4*>(bp + k * BROW);
            #pragma unroll
            for (int oi = 0; oi < TO; oi++) {
                acc[oi][0] = fmaf(av[oi], bv.x, acc[oi][0]);
                acc[oi][1] = fmaf(av[oi], bv.y, acc[oi][1]);
                acc[oi][2] = fmaf(av[oi], bv.z, acc[oi][2]);
                acc[oi][3] = fmaf(av[oi], bv.w, acc[oi][3]);
            }
        }

        // masked max over this thread's TO objects
        const int lim = img_l[i];
        #pragma unroll
        for (int wi = 0; wi < 4; wi++) {
            float m = NEG_BIG;
            #pragma unroll
            for (int oi = 0; oi < TO; oi++) {
                if (to * TO + oi < lim) m = fmaxf(m, acc[oi][wi]);
            }
            pm[to][tw * 4 + wi] = m;
        }
    }
    __syncthreads();

    // ---- max over object-tiles per word ----
    if (tid < W) {
        float m = pm[0][tid];
        #pragma unroll
        for (int t = 1; t < OT; t++) m = fmaxf(m, pm[t][tid]);
        wsum[tid] = m;
    }
    __syncthreads();

    // ---- deterministic serial sum over words, normalize, store ----
    if (tid == 0) {
        float s = 0.0f;
        #pragma unroll
        for (int w = 0; w < W; w++) s += wsum[w];
        float* out = SLOT ? g_s2 : g_s1;
        out[i * B + c] = s / (float)cap_l[c];
    }
}

// ---------------------------------------------------------------------------
// Hinge loss reduction over the B x B score matrix. One block of B threads.
// Deterministic: fixed-order loops + binary-tree reduce.
// ---------------------------------------------------------------------------
__global__ void loss_kernel(float* __restrict__ out, int B)
{
    __shared__ float diag[128];
    __shared__ float red[128];
    const int t = threadIdx.x;

    auto S = [&](int i, int j) -> float {
        int idx = i * B + j;
        return g_s1[idx] + g_s2[idx];
    };

    diag[t] = S(t, t);
    __syncthreads();

    const float dt = diag[t];
    float m1 = 0.0f;   // cost_s row max  (clamped at 0 by init)
    float m2 = 0.0f;   // cost_im col max
    for (int k = 0; k < B; k++) {
        if (k == t) continue;
        m1 = fmaxf(m1, MARGIN + S(t, k) - dt);
        m2 = fmaxf(m2, MARGIN + S(k, t) - dt);
    }
    red[t] = m1 + m2;
    __syncthreads();

    for (int s = 64; s > 0; s >>= 1) {
        if (t < s && t + s < B) red[t] += red[t + s];
        __syncthreads();
    }
    if (t == 0) out[0] = red[0];
}

// ---------------------------------------------------------------------------
// kernel_launch
// Inputs (metadata order):
//  0 im (B,36,128) f32 | 1 im_l (B) i32 | 2 s (B,50,128) f32 | 3 s_l (B) i32
//  4 pred (B,25,128)   | 5 pred_l      | 6 cap_o_pred (unused) | 7 cap_o_l (unused)
//  8 c_r_pred (B,30,128) | 9 c_r_l
// Output: scalar f32.
// ---------------------------------------------------------------------------
extern "C" void kernel_launch(void* const* d_in, const int* in_sizes, int n_in,
                              void* d_out, int out_size)
{
    const float* im     = (const float*)d_in[0];
    const int*   im_l   = (const int*)  d_in[1];
    const float* s      = (const float*)d_in[2];
    const int*   s_l    = (const int*)  d_in[3];
    const float* pred   = (const float*)d_in[4];
    const int*   pred_l = (const int*)  d_in[5];
    const float* crp    = (const float*)d_in[8];
    const int*   crl    = (const int*)  d_in[9];

    const int B = in_sizes[1];   // 128

    dim3 grid(B, B);

    // Term 1: O=36 (TO=4 -> OT=9, 117 threads), W=50 (WT=13).
    // AROW=36 (== OT*4), BROW=52 (WT*4): both ≡4 mod 8 -> ≤4-way STS conflicts.
    score_kernel<36, 50, 4, 36, 52, 0><<<grid, 128>>>(im, im_l, s, s_l, B);

    // Term 2: O=25 (TO=2 -> OT=13, 104 threads), W=30 (WT=8).
    // AROW=26, BROW=36 (pad 32->36 to dodge degree-32 store conflicts).
    score_kernel<25, 30, 2, 26, 36, 1><<<grid, 128>>>(pred, pred_l, crp, crl, B);

    loss_kernel<<<1, 128>>>((float*)d_out, B);
}

// round 2
// speedup vs baseline: 1.3415x; 1.3415x over previous
#include <cuda_runtime.h>
#include <cstdint>

#define MARGIN 0.2f
#define NEG_BIG (-3.0e38f)

// Scratch score matrices (B=128). No device allocation allowed -> device globals.
__device__ float g_s1[128 * 128];   // term-1 scores
__device__ float g_s2[128 * 128];   // TOTAL scores (term1 + term2), written by term-2 kernel

// Packed dual-FMA: acc.{lo,hi} += a.{lo,hi} * b.{lo,hi}  (one FFMA2 instruction)
#define FMA2(acc, a, b) \
    asm("fma.rn.f32x2 %0, %1, %2, %0;" : "+l"(acc) : "l"(a), "l"(b))

__device__ __forceinline__ float pairsum(unsigned long long v) {
    return __uint_as_float((unsigned)v) + __uint_as_float((unsigned)(v >> 32));
}

// ---------------------------------------------------------------------------
// score_kernel<O_REAL, TO, W_REAL, NCAP, SLOT>
//
// CTA = (image i = blockIdx.y, caption group c0 = NCAP*blockIdx.x).
// 4 warps; warp w owns objects [w*TO, w*TO+TO). Lanes own 64 "slots":
//   slot s in {lane, lane+32};  s -> (cap = s/WPC, word = s%WPC), WPC = 64/NCAP.
//
// A staged o-major in SMEM (stride 132 words, 16B aligned): warp-broadcast
// LDS.128 per object per 4k. B staged per k-half (64 k) with stride 68 words:
// conflict-free LDS.128 across lanes. Inner product uses f32x2 packing along
// k: acc holds even/odd-k partial sums; no repack ALU anywhere.
// ---------------------------------------------------------------------------
template<int O_REAL, int TO, int W_REAL, int NCAP, int SLOT>
__global__ __launch_bounds__(128, 4)
void score_kernel(const float* __restrict__ img,
                  const int*   __restrict__ img_l,
                  const float* __restrict__ cap,
                  const int*   __restrict__ cap_l,
                  int B)
{
    constexpr int D     = 128;
    constexpr int OP    = 4 * TO;          // padded object rows
    constexpr int SA    = 132;             // A row stride (words): 528B, 16B-aligned
    constexpr int SB    = 68;              // B half-row stride (words): 272B, 16B-aligned
    constexpr int SLOTS = 64;
    constexpr int WPC   = SLOTS / NCAP;    // word-slots per caption

    __shared__ __align__(16) float As[OP * SA];        // [o][k]   (full k)
    __shared__ __align__(16) float Bs[SLOTS * SB];     // [slot][k-half]
    __shared__ float pm[4][SLOTS];
    __shared__ float csum[2];

    const int i    = blockIdx.y;
    const int c0   = blockIdx.x * NCAP;
    const int tid  = threadIdx.x;
    const int wid  = tid >> 5;
    const int lane = tid & 31;
    const int obase = wid * TO;

    const float* __restrict__ Ag = img + (size_t)i * O_REAL * D;

    // ---- Stage A (o-major, coalesced reads, near-linear conflict-free STS) ----
    #pragma unroll 4
    for (int idx = tid; idx < O_REAL * D; idx += 128) {
        int o = idx >> 7, k = idx & 127;
        As[o * SA + k] = Ag[idx];
    }

    // Accumulators: f32x2 partial sums (even/odd k) per (object, slot-pair)
    unsigned long long acc[TO][2];
    #pragma unroll
    for (int oi = 0; oi < TO; oi++) { acc[oi][0] = 0ull; acc[oi][1] = 0ull; }

    #pragma unroll
    for (int h = 0; h < 2; h++) {
        __syncthreads();   // A visible (h=0) / previous half consumed (h=1)

        // ---- Stage B half: NCAP*W_REAL rows x 64 floats ----
        #pragma unroll 4
        for (int idx = tid; idx < NCAP * W_REAL * 64; idx += 128) {
            int r  = idx >> 6, kk = idx & 63;
            int ci = r / W_REAL, w = r - ci * W_REAL;
            int slot = ci * WPC + w;
            Bs[slot * SB + kk] = cap[((size_t)(c0 + ci) * W_REAL + w) * D + h * 64 + kk];
        }
        __syncthreads();

        const float* ap = As + obase * SA + h * 64;
        const float* bp0 = Bs + lane * SB;
        const float* bp1 = Bs + (lane + 32) * SB;

        #pragma unroll 4
        for (int k = 0; k < 64; k += 4) {
            ulonglong2 b0 = *reinterpret_cast<const ulonglong2*>(bp0 + k);
            ulonglong2 b1 = *reinterpret_cast<const ulonglong2*>(bp1 + k);
            #pragma unroll
            for (int oi = 0; oi < TO; oi++) {
                ulonglong2 a = *reinterpret_cast<const ulonglong2*>(ap + oi * SA + k);
                FMA2(acc[oi][0], a.x, b0.x);
                FMA2(acc[oi][0], a.y, b0.y);
                FMA2(acc[oi][1], a.x, b1.x);
                FMA2(acc[oi][1], a.y, b1.y);
            }
        }
    }

    // ---- Masked max over this warp's objects, per slot ----
    {
        const int lim = img_l[i];
        #pragma unroll
        for (int j = 0; j < 2; j++) {
            float m = NEG_BIG;
            #pragma unroll
            for (int oi = 0; oi < TO; oi++) {
                if (obase + oi < lim) m = fmaxf(m, pairsum(acc[oi][j]));
            }
            pm[wid][lane + 32 * j] = m;
        }
    }
    __syncthreads();

    // ---- Cross-warp max + per-caption word sum (warps 0 and 1) ----
    if (tid < SLOTS) {
        float m = fmaxf(fmaxf(pm[0][tid], pm[1][tid]),
                        fmaxf(pm[2][tid], pm[3][tid]));
        int w = tid % WPC;
        float v = (w < W_REAL) ? m : 0.0f;
        #pragma unroll
        for (int s = 16; s > 0; s >>= 1)
            v += __shfl_down_sync(0xffffffffu, v, s);
        if (lane == 0) csum[wid] = v;
    }
    __syncthreads();

    if (tid == 0) {
        if (NCAP == 1) {
            float r = (csum[0] + csum[1]) / (float)cap_l[c0];
            if (SLOT == 0) g_s1[i * B + c0] = r;
            else           g_s2[i * B + c0] = g_s1[i * B + c0] + r;
        } else {
            float r0 = csum[0] / (float)cap_l[c0];
            float r1 = csum[1] / (float)cap_l[c0 + 1];
            if (SLOT == 0) {
                g_s1[i * B + c0]     = r0;
                g_s1[i * B + c0 + 1] = r1;
            } else {
                g_s2[i * B + c0]     = g_s1[i * B + c0]     + r0;
                g_s2[i * B + c0 + 1] = g_s1[i * B + c0 + 1] + r1;
            }
        }
    }
}

// ---------------------------------------------------------------------------
// Hinge loss reduction over the B x B total-score matrix (g_s2).
// One block of B threads; deterministic fixed-order ops.
// ---------------------------------------------------------------------------
__global__ void loss_kernel(float* __restrict__ out, int B)
{
    __shared__ float diag[128];
    __shared__ float red[128];
    const int t = threadIdx.x;

    diag[t] = g_s2[t * B + t];
    __syncthreads();

    const float dt = diag[t];
    float m1 = 0.0f, m2 = 0.0f;
    for (int k = 0; k < B; k++) {
        if (k == t) continue;
        m1 = fmaxf(m1, MARGIN + g_s2[t * B + k] - dt);
        m2 = fmaxf(m2, MARGIN + g_s2[k * B + t] - dt);
    }
    red[t] = m1 + m2;
    __syncthreads();

    for (int s = 64; s > 0; s >>= 1) {
        if (t < s && t + s < B) red[t] += red[t + s];
        __syncthreads();
    }
    if (t == 0) out[0] = red[0];
}

// ---------------------------------------------------------------------------
// Inputs (metadata order):
//  0 im (B,36,128) f32 | 1 im_l (B) i32 | 2 s (B,50,128) f32 | 3 s_l (B) i32
//  4 pred (B,25,128)   | 5 pred_l       | 6 cap_o_pred (unused) | 7 cap_o_l (unused)
//  8 c_r_pred (B,30,128) | 9 c_r_l
// Output: scalar f32.
// ---------------------------------------------------------------------------
extern "C" void kernel_launch(void* const* d_in, const int* in_sizes, int n_in,
                              void* d_out, int out_size)
{
    const float* im     = (const float*)d_in[0];
    const int*   im_l   = (const int*)  d_in[1];
    const float* s      = (const float*)d_in[2];
    const int*   s_l    = (const int*)  d_in[3];
    const float* pred   = (const float*)d_in[4];
    const int*   pred_l = (const int*)  d_in[5];
    const float* crp    = (const float*)d_in[8];
    const int*   crl    = (const int*)  d_in[9];

    const int B = in_sizes[1];   // 128

    // Term 1: O=36 (4 warps x TO=9), W=50 (1 caption, 64 slots), writes g_s1.
    score_kernel<36, 9, 50, 1, 0><<<dim3(B, B), 128>>>(im, im_l, s, s_l, B);

    // Term 2: O=25 (TO=7, padded 28), W=30, 2 captions/CTA; writes g_s2 = g_s1 + term2.
    score_kernel<25, 7, 30, 2, 1><<<dim3(B / 2, B), 128>>>(pred, pred_l, crp, crl, B);

    loss_kernel<<<1, 128>>>((float*)d_out, B);
}

// round 4
// speedup vs baseline: 1.7975x; 1.3399x over previous
#include <cuda_runtime.h>
#include <cstdint>

#define MARGIN 0.2f
#define NEG_BIG (-3.0e38f)

// Scratch score matrices. No device allocation allowed -> device globals.
__device__ float g_s1[128 * 128];   // term-1 scores
__device__ float g_s2[128 * 128];   // TOTAL scores (term1 + term2)

__device__ __forceinline__ uint32_t tf32_rna(float a) {
    uint32_t u;
    asm("cvt.rna.tf32.f32 %0, %1;" : "=r"(u) : "f"(a));
    return u;
}

// m16n8k8 tf32 MMA (sm_80+ legacy path; no sm_103a features needed)
#define MMA_TF32(d, a, b) \
    asm volatile("mma.sync.aligned.m16n8k8.row.col.f32.tf32.tf32.f32 " \
        "{%0,%1,%2,%3}, {%4,%5,%6,%7}, {%8,%9}, {%0,%1,%2,%3};" \
        : "+f"((d)[0]), "+f"((d)[1]), "+f"((d)[2]), "+f"((d)[3]) \
        : "r"((a)[0]), "r"((a)[1]), "r"((a)[2]), "r"((a)[3]), \
          "r"((b)[0]), "r"((b)[1]))

// ---- SMEM layout (dynamic). Strides padded so fragment LDS is conflict-free:
// bank = (row*4 + k) % 32, rows l>>2 distinct, k l&3 -> all 32 banks distinct.
static constexpr int SA = 132;                    // A row stride (full K=128)
static constexpr int SB = 68;                     // B row stride (K chunk = 64)
static constexpr int OFF_A_HI = 0;                // 128*132*4 = 67584
static constexpr int OFF_A_LO = 67584;            // 67584
static constexpr int OFF_B_HI = 135168;           // 128*68*4 = 34816
static constexpr int OFF_B_LO = 169984;           // 34816
static constexpr int SMEM_TOTAL = 204800;         // 200 KB

// ---------------------------------------------------------------------------
// score_tc<O, W, NIMG, NCAP, CSLOT, SLOT>
// CTA: M=128 rows = NIMG images x O objects (zero-padded),
//      N=128 cols = NCAP captions x CSLOT word slots (zero-padded).
// 3-pass tf32: D = Ahi*Bhi + Ahi*Blo + Alo*Bhi  (fp32-grade accuracy).
// 8 warps: warp (wm = w&3, wn = w>>2) owns rows [wm*32,+32) x cols [wn*64,+64).
// Epilogue: regs -> SMEM col-major -> masked object max -> word sums.
// ---------------------------------------------------------------------------
template<int O, int W, int NIMG, int NCAP, int CSLOT, int SLOT>
__global__ __launch_bounds__(256)
void score_tc(const float* __restrict__ img,
              const int*   __restrict__ img_l,
              const float* __restrict__ cap,
              const int*   __restrict__ cap_l,
              int B)
{
    extern __shared__ char smem[];
    float* Ah = reinterpret_cast<float*>(smem + OFF_A_HI);
    float* Al = reinterpret_cast<float*>(smem + OFF_A_LO);
    float* Bh = reinterpret_cast<float*>(smem + OFF_B_HI);
    float* Bl = reinterpret_cast<float*>(smem + OFF_B_LO);

    const int tid  = threadIdx.x;
    const int wid  = tid >> 5;
    const int lane = tid & 31;
    const int gr   = lane >> 2;      // group row
    const int tc   = lane & 3;       // thread col in group

    const int gi = blockIdx.y;                 // image group
    const int cg = blockIdx.x;                 // caption group
    const int ng = min(NIMG, B - gi * NIMG);
    const int arows = ng * O;

    // ---- Stage A (full K=128), hi/lo tf32 split ----
    {
        const float* Ag = img + (size_t)gi * NIMG * O * 128;
        #pragma unroll 4
        for (int u = tid; u < 128 * 32; u += 256) {
            int r = u >> 5, kq = (u & 31) << 2;
            float4 v = make_float4(0.f, 0.f, 0.f, 0.f);
            if (r < arows) v = *reinterpret_cast<const float4*>(Ag + r * 128 + kq);
            uint4 hv, lv;
            hv.x = tf32_rna(v.x); lv.x = tf32_rna(v.x - __uint_as_float(hv.x));
            hv.y = tf32_rna(v.y); lv.y = tf32_rna(v.y - __uint_as_float(hv.y));
            hv.z = tf32_rna(v.z); lv.z = tf32_rna(v.z - __uint_as_float(hv.z));
            hv.w = tf32_rna(v.w); lv.w = tf32_rna(v.w - __uint_as_float(hv.w));
            *reinterpret_cast<uint4*>(Ah + r * SA + kq) = hv;
            *reinterpret_cast<uint4*>(Al + r * SA + kq) = lv;
        }
    }

    // Warp tile origin
    const int wm = wid & 3, wn = wid >> 2;
    const int m0 = wm * 32, n0 = wn * 64;

    float acc[2][8][4];
    #pragma unroll
    for (int ms = 0; ms < 2; ms++)
        #pragma unroll
        for (int ns = 0; ns < 8; ns++)
            #pragma unroll
            for (int j = 0; j < 4; j++) acc[ms][ns][j] = 0.0f;

    // ---- K chunks ----
    #pragma unroll
    for (int chunk = 0; chunk < 2; chunk++) {
        __syncthreads();   // A ready (c0) / previous B consumed (c1)

        // Stage B chunk (64 k), hi/lo split, n-major rows
        #pragma unroll 2
        for (int u = tid; u < 128 * 16; u += 256) {
            int n = u >> 4, kq = (u & 15) << 2;
            int ci = n / CSLOT, w = n % CSLOT;
            float4 v = make_float4(0.f, 0.f, 0.f, 0.f);
            if (w < W)
                v = *reinterpret_cast<const float4*>(
                        cap + ((size_t)(cg * NCAP + ci) * W + w) * 128 + chunk * 64 + kq);
            uint4 hv, lv;
            hv.x = tf32_rna(v.x); lv.x = tf32_rna(v.x - __uint_as_float(hv.x));
            hv.y = tf32_rna(v.y); lv.y = tf32_rna(v.y - __uint_as_float(hv.y));
            hv.z = tf32_rna(v.z); lv.z = tf32_rna(v.z - __uint_as_float(hv.z));
            hv.w = tf32_rna(v.w); lv.w = tf32_rna(v.w - __uint_as_float(hv.w));
            *reinterpret_cast<uint4*>(Bh + n * SB + kq) = hv;
            *reinterpret_cast<uint4*>(Bl + n * SB + kq) = lv;
        }
        __syncthreads();

        const uint32_t* Ahu = reinterpret_cast<const uint32_t*>(Ah);
        const uint32_t* Alu = reinterpret_cast<const uint32_t*>(Al);
        const uint32_t* Bhu = reinterpret_cast<const uint32_t*>(Bh);
        const uint32_t* Blu = reinterpret_cast<const uint32_t*>(Bl);

        #pragma unroll
        for (int kk = 0; kk < 64; kk += 8) {
            const int k0 = chunk * 64 + kk;

            uint32_t ah[2][4], al[2][4];
            #pragma unroll
            for (int ms = 0; ms < 2; ms++) {
                int r = m0 + ms * 16 + gr;
                ah[ms][0] = Ahu[r * SA + k0 + tc];
                ah[ms][1] = Ahu[(r + 8) * SA + k0 + tc];
                ah[ms][2] = Ahu[r * SA + k0 + tc + 4];
                ah[ms][3] = Ahu[(r + 8) * SA + k0 + tc + 4];
                al[ms][0] = Alu[r * SA + k0 + tc];
                al[ms][1] = Alu[(r + 8) * SA + k0 + tc];
                al[ms][2] = Alu[r * SA + k0 + tc + 4];
                al[ms][3] = Alu[(r + 8) * SA + k0 + tc + 4];
            }
            uint32_t bh[8][2], bl[8][2];
            #pragma unroll
            for (int ns = 0; ns < 8; ns++) {
                int n = n0 + ns * 8 + gr;
                bh[ns][0] = Bhu[n * SB + kk + tc];
                bh[ns][1] = Bhu[n * SB + kk + tc + 4];
                bl[ns][0] = Blu[n * SB + kk + tc];
                bl[ns][1] = Blu[n * SB + kk + tc + 4];
            }
            #pragma unroll
            for (int ms = 0; ms < 2; ms++)
                #pragma unroll
                for (int ns = 0; ns < 8; ns++) {
                    MMA_TF32(acc[ms][ns], ah[ms], bh[ns]);
                    MMA_TF32(acc[ms][ns], ah[ms], bl[ns]);
                    MMA_TF32(acc[ms][ns], al[ms], bh[ns]);
                }
        }
    }
    __syncthreads();   // all MMAs done; A region reusable

    // ---- D (regs) -> SMEM col-major [col][row], stride SA ----
    float* Dcol = Ah;  // 128*132*4 = 67584 bytes, fits A_hi region
    #pragma unroll
    for (int ms = 0; ms < 2; ms++) {
        int r = m0 + ms * 16 + gr;
        #pragma unroll
        for (int ns = 0; ns < 8; ns++) {
            int c = n0 + ns * 8 + 2 * tc;
            Dcol[c * SA + r]           = acc[ms][ns][0];
            Dcol[(c + 1) * SA + r]     = acc[ms][ns][1];
            Dcol[c * SA + r + 8]       = acc[ms][ns][2];
            Dcol[(c + 1) * SA + r + 8] = acc[ms][ns][3];
        }
    }
    __syncthreads();

    // ---- Masked max over objects per (image, col) ----
    float* pooled = Bh;   // NIMG*128 floats
    for (int u = tid; u < NIMG * 128; u += 256) {
        int j = u >> 7, c = u & 127;
        int lim = (j < ng) ? img_l[gi * NIMG + j] : 0;
        float m = NEG_BIG;
        const float* col = Dcol + c * SA + j * O;
        for (int r = 0; r < lim; r++) m = fmaxf(m, col[r]);
        pooled[u] = m;
    }
    __syncthreads();

    // ---- Per-(image, caption) word sums -> global scores ----
    if (tid < NIMG * NCAP) {
        int j = tid / NCAP, ci = tid % NCAP;
        if (j < ng) {
            float s = 0.0f;
            #pragma unroll
            for (int w = 0; w < W; w++) s += pooled[j * 128 + ci * CSLOT + w];
            int i = gi * NIMG + j, c = cg * NCAP + ci;
            float r = s / (float)cap_l[c];
            if (SLOT == 0) g_s1[i * B + c] = r;
            else           g_s2[i * B + c] = g_s1[i * B + c] + r;
        }
    }
}

// ---------------------------------------------------------------------------
// Hinge loss over B x B total scores (g_s2). Deterministic.
// ---------------------------------------------------------------------------
__global__ void loss_kernel(float* __restrict__ out, int B)
{
    __shared__ float red[128];
    const int t = threadIdx.x;
    const float dt = g_s2[t * B + t];
    float m1 = 0.0f, m2 = 0.0f;
    for (int k = 0; k < B; k++) {
        if (k == t) continue;
        m1 = fmaxf(m1, MARGIN + g_s2[t * B + k] - dt);
        m2 = fmaxf(m2, MARGIN + g_s2[k * B + t] - dt);
    }
    red[t] = m1 + m2;
    __syncthreads();
    for (int s = 64; s > 0; s >>= 1) {
        if (t < s && t + s < B) red[t] += red[t + s];
        __syncthreads();
    }
    if (t == 0) out[0] = red[0];
}

// ---------------------------------------------------------------------------
// Inputs (metadata order):
//  0 im (B,36,128) f32 | 1 im_l (B) i32 | 2 s (B,50,128) f32 | 3 s_l (B) i32
//  4 pred (B,25,128)   | 5 pred_l       | 6/7 unused | 8 c_r_pred (B,30,128) | 9 c_r_l
// Output: scalar f32.
// ---------------------------------------------------------------------------
extern "C" void kernel_launch(void* const* d_in, const int* in_sizes, int n_in,
                              void* d_out, int out_size)
{
    const float* im     = (const float*)d_in[0];
    const int*   im_l   = (const int*)  d_in[1];
    const float* s      = (const float*)d_in[2];
    const int*   s_l    = (const int*)  d_in[3];
    const float* pred   = (const float*)d_in[4];
    const int*   pred_l = (const int*)  d_in[5];
    const float* crp    = (const float*)d_in[8];
    const int*   crl    = (const int*)  d_in[9];

    const int B = in_sizes[1];   // 128

    cudaFuncSetAttribute(score_tc<36, 50, 3, 2, 64, 0>,
                         cudaFuncAttributeMaxDynamicSharedMemorySize, SMEM_TOTAL);
    cudaFuncSetAttribute(score_tc<25, 30, 5, 4, 32, 1>,
                         cudaFuncAttributeMaxDynamicSharedMemorySize, SMEM_TOTAL);

    // Term 1: 3 images x 2 captions per CTA -> grid (64, 43)
    score_tc<36, 50, 3, 2, 64, 0><<<dim3(B / 2, (B + 2) / 3), 256, SMEM_TOTAL>>>(
        im, im_l, s, s_l, B);

    // Term 2: 5 images x 4 captions per CTA -> grid (32, 26)
    score_tc<25, 30, 5, 4, 32, 1><<<dim3(B / 4, (B + 4) / 5), 256, SMEM_TOTAL>>>(
        pred, pred_l, crp, crl, B);

    loss_kernel<<<1, 128>>>((float*)d_out, B);
}

// round 5
// speedup vs baseline: 2.3255x; 1.2938x over previous
#include <cuda_runtime.h>
#include <cstdint>

#define MARGIN 0.2f
#define NEG_BIG (-3.0e38f)

// Scratch score matrices. No device allocation allowed -> device globals.
__device__ float g_s1[128 * 128];   // term-1 scores
__device__ float g_s2[128 * 128];   // TOTAL scores (term1 + term2)

__device__ __forceinline__ uint32_t tf32_rna(float a) {
    uint32_t u;
    asm("cvt.rna.tf32.f32 %0, %1;" : "=r"(u) : "f"(a));
    return u;
}

// m16n8k8 tf32 MMA (sm_80+ legacy path; compiles for base sm_103)
#define MMA_TF32(d, a, b) \
    asm volatile("mma.sync.aligned.m16n8k8.row.col.f32.tf32.tf32.f32 " \
        "{%0,%1,%2,%3}, {%4,%5,%6,%7}, {%8,%9}, {%0,%1,%2,%3};" \
        : "+f"((d)[0]), "+f"((d)[1]), "+f"((d)[2]), "+f"((d)[3]) \
        : "r"((a)[0]), "r"((a)[1]), "r"((a)[2]), "r"((a)[3]), \
          "r"((b)[0]), "r"((b)[1]))

// ---- SMEM: K chunked by 32 for BOTH operands. Row stride 36 (mod 32 == 4)
// makes every fragment LDS conflict-free: bank = 4*gr + tc covers 32 banks.
static constexpr int KC = 32;                       // K chunk
static constexpr int SA = 36;                       // A row stride (floats)
static constexpr int SB = 36;                       // B row stride (floats)
static constexpr int OFF_A_HI = 0;                  // 128*36*4 = 18432 B
static constexpr int OFF_A_LO = 18432;
static constexpr int OFF_B_HI = 36864;
static constexpr int OFF_B_LO = 55296;
static constexpr int SMEM_TOTAL = 73728;            // 72 KB -> 2 CTAs/SM
static constexpr int SD = 132;                      // epilogue Dcol stride

// ---------------------------------------------------------------------------
// score_tc<O, W, NIMG, NCAP, CSLOT, SLOT>
// CTA: M=128 rows = NIMG images x O objects (zero-padded),
//      N=128 cols = NCAP captions x CSLOT word slots (zero-padded).
// 3-pass tf32: D = Ahi*Bhi + Ahi*Blo + Alo*Bhi (fp32-grade accuracy).
// 8 warps: warp (wm=w&3, wn=w>>2) owns rows [wm*32,+32) x cols [wn*64,+64).
// ---------------------------------------------------------------------------
template<int O, int W, int NIMG, int NCAP, int CSLOT, int SLOT>
__global__ __launch_bounds__(256, 2)
void score_tc(const float* __restrict__ img,
              const int*   __restrict__ img_l,
              const float* __restrict__ cap,
              const int*   __restrict__ cap_l,
              int B)
{
    extern __shared__ char smem[];
    float* Ah = reinterpret_cast<float*>(smem + OFF_A_HI);
    float* Al = reinterpret_cast<float*>(smem + OFF_A_LO);
    float* Bh = reinterpret_cast<float*>(smem + OFF_B_HI);
    float* Bl = reinterpret_cast<float*>(smem + OFF_B_LO);

    const int tid  = threadIdx.x;
    const int wid  = tid >> 5;
    const int lane = tid & 31;
    const int gr   = lane >> 2;
    const int tc   = lane & 3;

    const int gi = blockIdx.y;
    const int cg = blockIdx.x;
    const int ng = min(NIMG, B - gi * NIMG);
    const int arows = ng * O;

    const int wm = wid & 3, wn = wid >> 2;
    const int m0 = wm * 32, n0 = wn * 64;

    float acc[2][8][4];
    #pragma unroll
    for (int ms = 0; ms < 2; ms++)
        #pragma unroll
        for (int ns = 0; ns < 8; ns++)
            #pragma unroll
            for (int j = 0; j < 4; j++) acc[ms][ns][j] = 0.0f;

    const float* Ag = img + (size_t)gi * NIMG * O * 128;

    #pragma unroll 1
    for (int chunk = 0; chunk < 4; chunk++) {
        const int k0g = chunk * KC;
        __syncthreads();   // previous chunk consumed

        // ---- Stage A chunk: 128 rows x 32 k, hi/lo tf32 split ----
        #pragma unroll
        for (int u = tid; u < 128 * 8; u += 256) {
            int r = u >> 3, kq = (u & 7) << 2;
            float4 v = make_float4(0.f, 0.f, 0.f, 0.f);
            if (r < arows)
                v = *reinterpret_cast<const float4*>(Ag + r * 128 + k0g + kq);
            uint4 hv, lv;
            hv.x = tf32_rna(v.x); lv.x = tf32_rna(v.x - __uint_as_float(hv.x));
            hv.y = tf32_rna(v.y); lv.y = tf32_rna(v.y - __uint_as_float(hv.y));
            hv.z = tf32_rna(v.z); lv.z = tf32_rna(v.z - __uint_as_float(hv.z));
            hv.w = tf32_rna(v.w); lv.w = tf32_rna(v.w - __uint_as_float(hv.w));
            *reinterpret_cast<uint4*>(Ah + r * SA + kq) = hv;
            *reinterpret_cast<uint4*>(Al + r * SA + kq) = lv;
        }
        // ---- Stage B chunk: 128 n-rows x 32 k ----
        #pragma unroll
        for (int u = tid; u < 128 * 8; u += 256) {
            int n = u >> 3, kq = (u & 7) << 2;
            int ci = n / CSLOT, w = n % CSLOT;
            float4 v = make_float4(0.f, 0.f, 0.f, 0.f);
            if (w < W)
                v = *reinterpret_cast<const float4*>(
                        cap + ((size_t)(cg * NCAP + ci) * W + w) * 128 + k0g + kq);
            uint4 hv, lv;
            hv.x = tf32_rna(v.x); lv.x = tf32_rna(v.x - __uint_as_float(hv.x));
            hv.y = tf32_rna(v.y); lv.y = tf32_rna(v.y - __uint_as_float(hv.y));
            hv.z = tf32_rna(v.z); lv.z = tf32_rna(v.z - __uint_as_float(hv.z));
            hv.w = tf32_rna(v.w); lv.w = tf32_rna(v.w - __uint_as_float(hv.w));
            *reinterpret_cast<uint4*>(Bh + n * SB + kq) = hv;
            *reinterpret_cast<uint4*>(Bl + n * SB + kq) = lv;
        }
        __syncthreads();

        const uint32_t* Ahu = reinterpret_cast<const uint32_t*>(Ah);
        const uint32_t* Alu = reinterpret_cast<const uint32_t*>(Al);
        const uint32_t* Bhu = reinterpret_cast<const uint32_t*>(Bh);
        const uint32_t* Blu = reinterpret_cast<const uint32_t*>(Bl);

        #pragma unroll
        for (int kk = 0; kk < KC; kk += 8) {
            uint32_t ah[2][4], al[2][4];
            #pragma unroll
            for (int ms = 0; ms < 2; ms++) {
                int r = m0 + ms * 16 + gr;
                ah[ms][0] = Ahu[r * SA + kk + tc];
                ah[ms][1] = Ahu[(r + 8) * SA + kk + tc];
                ah[ms][2] = Ahu[r * SA + kk + tc + 4];
                ah[ms][3] = Ahu[(r + 8) * SA + kk + tc + 4];
                al[ms][0] = Alu[r * SA + kk + tc];
                al[ms][1] = Alu[(r + 8) * SA + kk + tc];
                al[ms][2] = Alu[r * SA + kk + tc + 4];
                al[ms][3] = Alu[(r + 8) * SA + kk + tc + 4];
            }
            uint32_t bh[8][2], bl[8][2];
            #pragma unroll
            for (int ns = 0; ns < 8; ns++) {
                int n = n0 + ns * 8 + gr;
                bh[ns][0] = Bhu[n * SB + kk + tc];
                bh[ns][1] = Bhu[n * SB + kk + tc + 4];
                bl[ns][0] = Blu[n * SB + kk + tc];
                bl[ns][1] = Blu[n * SB + kk + tc + 4];
            }
            #pragma unroll
            for (int ms = 0; ms < 2; ms++)
                #pragma unroll
                for (int ns = 0; ns < 8; ns++) {
                    MMA_TF32(acc[ms][ns], ah[ms], bh[ns]);
                    MMA_TF32(acc[ms][ns], ah[ms], bl[ns]);
                    MMA_TF32(acc[ms][ns], al[ms], bh[ns]);
                }
        }
    }
    __syncthreads();   // MMAs done; whole smem reusable

    // ---- D (regs) -> SMEM col-major [col][row], stride SD ----
    float* Dcol = reinterpret_cast<float*>(smem);          // 128*132*4 = 67584 B
    float* pooled = reinterpret_cast<float*>(smem + 69632); // NIMG*128 floats
    #pragma unroll
    for (int ms = 0; ms < 2; ms++) {
        int r = m0 + ms * 16 + gr;
        #pragma unroll
        for (int ns = 0; ns < 8; ns++) {
            int c = n0 + ns * 8 + 2 * tc;
            Dcol[c * SD + r]           = acc[ms][ns][0];
            Dcol[(c + 1) * SD + r]     = acc[ms][ns][1];
            Dcol[c * SD + r + 8]       = acc[ms][ns][2];
            Dcol[(c + 1) * SD + r + 8] = acc[ms][ns][3];
        }
    }
    __syncthreads();

    // ---- Masked max over objects per (image, col) ----
    for (int u = tid; u < NIMG * 128; u += 256) {
        int j = u >> 7, c = u & 127;
        int lim = (j < ng) ? img_l[gi * NIMG + j] : 0;
        float m = NEG_BIG;
        const float* col = Dcol + c * SD + j * O;
        for (int r = 0; r < lim; r++) m = fmaxf(m, col[r]);
        pooled[u] = m;
    }
    __syncthreads();

    // ---- Per-(image, caption) word sums -> global scores ----
    if (tid < NIMG * NCAP) {
        int j = tid / NCAP, ci = tid % NCAP;
        if (j < ng) {
            float s = 0.0f;
            #pragma unroll
            for (int w = 0; w < W; w++) s += pooled[j * 128 + ci * CSLOT + w];
            int i = gi * NIMG + j, c = cg * NCAP + ci;
            float r = s / (float)cap_l[c];
            if (SLOT == 0) g_s1[i * B + c] = r;
            else           g_s2[i * B + c] = g_s1[i * B + c] + r;
        }
    }
}

// ---------------------------------------------------------------------------
// Hinge loss over B x B total scores (g_s2). Deterministic.
// ---------------------------------------------------------------------------
__global__ void loss_kernel(float* __restrict__ out, int B)
{
    __shared__ float red[128];
    const int t = threadIdx.x;
    const float dt = g_s2[t * B + t];
    float m1 = 0.0f, m2 = 0.0f;
    for (int k = 0; k < B; k++) {
        if (k == t) continue;
        m1 = fmaxf(m1, MARGIN + g_s2[t * B + k] - dt);
        m2 = fmaxf(m2, MARGIN + g_s2[k * B + t] - dt);
    }
    red[t] = m1 + m2;
    __syncthreads();
    for (int s = 64; s > 0; s >>= 1) {
        if (t < s && t + s < B) red[t] += red[t + s];
        __syncthreads();
    }
    if (t == 0) out[0] = red[0];
}

// ---------------------------------------------------------------------------
// Inputs (metadata order):
//  0 im (B,36,128) f32 | 1 im_l (B) i32 | 2 s (B,50,128) f32 | 3 s_l (B) i32
//  4 pred (B,25,128)   | 5 pred_l       | 6/7 unused | 8 c_r_pred (B,30,128) | 9 c_r_l
// Output: scalar f32.
// ---------------------------------------------------------------------------
extern "C" void kernel_launch(void* const* d_in, const int* in_sizes, int n_in,
                              void* d_out, int out_size)
{
    const float* im     = (const float*)d_in[0];
    const int*   im_l   = (const int*)  d_in[1];
    const float* s      = (const float*)d_in[2];
    const int*   s_l    = (const int*)  d_in[3];
    const float* pred   = (const float*)d_in[4];
    const int*   pred_l = (const int*)  d_in[5];
    const float* crp    = (const float*)d_in[8];
    const int*   crl    = (const int*)  d_in[9];

    const int B = in_sizes[1];   // 128

    cudaFuncSetAttribute(score_tc<36, 50, 3, 2, 64, 0>,
                         cudaFuncAttributeMaxDynamicSharedMemorySize, SMEM_TOTAL);
    cudaFuncSetAttribute(score_tc<25, 30, 5, 4, 32, 1>,
                         cudaFuncAttributeMaxDynamicSharedMemorySize, SMEM_TOTAL);

    // Term 1: 3 images x 2 captions per CTA -> grid (64, 43)
    score_tc<36, 50, 3, 2, 64, 0><<<dim3(B / 2, (B + 2) / 3), 256, SMEM_TOTAL>>>(
        im, im_l, s, s_l, B);

    // Term 2: 5 images x 4 captions per CTA -> grid (32, 26)
    score_tc<25, 30, 5, 4, 32, 1><<<dim3(B / 4, (B + 4) / 5), 256, SMEM_TOTAL>>>(
        pred, pred_l, crp, crl, B);

    loss_kernel<<<1, 128>>>((float*)d_out, B);
}

// round 6
// speedup vs baseline: 3.5462x; 1.5249x over previous
#include <cuda_runtime.h>
#include <cstdint>

#define MARGIN 0.2f
#define NEG_BIG (-3.0e38f)

// Scratch score matrices. No device allocation allowed -> device globals.
__device__ float g_s1[128 * 128];   // term-1 scores
__device__ float g_s2[128 * 128];   // TOTAL scores (term1 + term2)

// bf16 round of an f32, returned as f32 (low 16 mantissa bits cleared).
__device__ __forceinline__ float bf16_hi(float a) {
    uint16_t u;
    asm("cvt.rn.bf16.f32 %0, %1;" : "=h"(u) : "f"(a));
    return __uint_as_float(((uint32_t)u) << 16);
}
// Pack two f32 into bf16x2 word: {hi = bf16(b), lo = bf16(a)}.
__device__ __forceinline__ uint32_t pack_bf16x2(float a, float b) {
    uint32_t r;
    asm("cvt.rn.bf16x2.f32 %0, %1, %2;" : "=r"(r) : "f"(b), "f"(a));
    return r;
}

// m16n8k16 bf16 MMA, fp32 accumulate (sm_80+ path; compiles for base sm_103)
#define MMA_BF16(d, a, b) \
    asm volatile("mma.sync.aligned.m16n8k16.row.col.f32.bf16.bf16.f32 " \
        "{%0,%1,%2,%3}, {%4,%5,%6,%7}, {%8,%9}, {%0,%1,%2,%3};" \
        : "+f"((d)[0]), "+f"((d)[1]), "+f"((d)[2]), "+f"((d)[3]) \
        : "r"((a)[0]), "r"((a)[1]), "r"((a)[2]), "r"((a)[3]), \
          "r"((b)[0]), "r"((b)[1]))

// ---- SMEM: K chunked by 64 (32 bf16x2 words/row). Row stride 36 words
// (36 mod 32 == 4) -> fragment LDS bank = 4*gr + tc covers all 32 banks.
static constexpr int KC = 64;                       // K chunk (elements)
static constexpr int SW = 36;                       // row stride (words)
static constexpr int OFF_A_HI = 0;                  // 128*36*4 = 18432 B
static constexpr int OFF_A_LO = 18432;
static constexpr int OFF_B_HI = 36864;
static constexpr int OFF_B_LO = 55296;
static constexpr int SMEM_TOTAL = 73728;            // 72 KB -> 2 CTAs/SM
static constexpr int SD = 132;                      // epilogue Dcol stride

// ---------------------------------------------------------------------------
// score_tc<O, W, NIMG, NCAP, CSLOT, SLOT>
// CTA: M=128 rows = NIMG images x O objects (zero-padded),
//      N=128 cols = NCAP captions x CSLOT word slots (zero-padded).
// 3-pass bf16 split: D = Ahi*Bhi + Ahi*Blo + Alo*Bhi (~1e-5 accuracy).
// 8 warps: warp (wm=w&3, wn=w>>2) owns rows [wm*32,+32) x cols [wn*64,+64).
// ---------------------------------------------------------------------------
template<int O, int W, int NIMG, int NCAP, int CSLOT, int SLOT>
__global__ __launch_bounds__(256, 2)
void score_tc(const float* __restrict__ img,
              const int*   __restrict__ img_l,
              const float* __restrict__ cap,
              const int*   __restrict__ cap_l,
              int B)
{
    extern __shared__ char smem[];
    uint32_t* Ah = reinterpret_cast<uint32_t*>(smem + OFF_A_HI);
    uint32_t* Al = reinterpret_cast<uint32_t*>(smem + OFF_A_LO);
    uint32_t* Bh = reinterpret_cast<uint32_t*>(smem + OFF_B_HI);
    uint32_t* Bl = reinterpret_cast<uint32_t*>(smem + OFF_B_LO);

    const int tid  = threadIdx.x;
    const int wid  = tid >> 5;
    const int lane = tid & 31;
    const int gr   = lane >> 2;
    const int tc   = lane & 3;

    const int gi = blockIdx.y;
    const int cg = blockIdx.x;
    const int ng = min(NIMG, B - gi * NIMG);
    const int arows = ng * O;

    const int wm = wid & 3, wn = wid >> 2;
    const int m0 = wm * 32, n0 = wn * 64;

    float acc[2][8][4];
    #pragma unroll
    for (int ms = 0; ms < 2; ms++)
        #pragma unroll
        for (int ns = 0; ns < 8; ns++)
            #pragma unroll
            for (int j = 0; j < 4; j++) acc[ms][ns][j] = 0.0f;

    const float* Ag = img + (size_t)gi * NIMG * O * 128;

    #pragma unroll 1
    for (int chunk = 0; chunk < 2; chunk++) {
        const int k0g = chunk * KC;
        __syncthreads();   // previous chunk consumed

        // ---- Stage A chunk: 128 rows x 64 k -> hi/lo bf16x2 words ----
        #pragma unroll
        for (int u = tid; u < 128 * 16; u += 256) {
            int r = u >> 4, kq = (u & 15) << 2;     // k offset in chunk (mult of 4)
            float4 v = make_float4(0.f, 0.f, 0.f, 0.f);
            if (r < arows)
                v = *reinterpret_cast<const float4*>(Ag + r * 128 + k0g + kq);
            float hx = bf16_hi(v.x), hy = bf16_hi(v.y);
            float hz = bf16_hi(v.z), hw = bf16_hi(v.w);
            uint2 hwd, lwd;
            hwd.x = (__float_as_uint(hy) & 0xFFFF0000u) | (__float_as_uint(hx) >> 16);
            hwd.y = (__float_as_uint(hw) & 0xFFFF0000u) | (__float_as_uint(hz) >> 16);
            lwd.x = pack_bf16x2(v.x - hx, v.y - hy);
            lwd.y = pack_bf16x2(v.z - hz, v.w - hw);
            int wi = r * SW + (kq >> 1);
            *reinterpret_cast<uint2*>(Ah + wi) = hwd;
            *reinterpret_cast<uint2*>(Al + wi) = lwd;
        }
        // ---- Stage B chunk: 128 n-rows x 64 k ----
        #pragma unroll
        for (int u = tid; u < 128 * 16; u += 256) {
            int n = u >> 4, kq = (u & 15) << 2;
            int ci = n / CSLOT, w = n % CSLOT;
            float4 v = make_float4(0.f, 0.f, 0.f, 0.f);
            if (w < W)
                v = *reinterpret_cast<const float4*>(
                        cap + ((size_t)(cg * NCAP + ci) * W + w) * 128 + k0g + kq);
            float hx = bf16_hi(v.x), hy = bf16_hi(v.y);
            float hz = bf16_hi(v.z), hw = bf16_hi(v.w);
            uint2 hwd, lwd;
            hwd.x = (__float_as_uint(hy) & 0xFFFF0000u) | (__float_as_uint(hx) >> 16);
            hwd.y = (__float_as_uint(hw) & 0xFFFF0000u) | (__float_as_uint(hz) >> 16);
            lwd.x = pack_bf16x2(v.x - hx, v.y - hy);
            lwd.y = pack_bf16x2(v.z - hz, v.w - hw);
            int wi = n * SW + (kq >> 1);
            *reinterpret_cast<uint2*>(Bh + wi) = hwd;
            *reinterpret_cast<uint2*>(Bl + wi) = lwd;
        }
        __syncthreads();

        // ---- 4 k-steps of 16 per chunk ----
        #pragma unroll
        for (int kk = 0; kk < KC / 2; kk += 8) {    // word offset per kstep
            uint32_t ah[2][4], al[2][4];
            #pragma unroll
            for (int ms = 0; ms < 2; ms++) {
                int r = m0 + ms * 16 + gr;
                ah[ms][0] = Ah[r * SW + kk + tc];
                ah[ms][1] = Ah[(r + 8) * SW + kk + tc];
                ah[ms][2] = Ah[r * SW + kk + tc + 4];
                ah[ms][3] = Ah[(r + 8) * SW + kk + tc + 4];
                al[ms][0] = Al[r * SW + kk + tc];
                al[ms][1] = Al[(r + 8) * SW + kk + tc];
                al[ms][2] = Al[r * SW + kk + tc + 4];
                al[ms][3] = Al[(r + 8) * SW + kk + tc + 4];
            }
            uint32_t bh[8][2], bl[8][2];
            #pragma unroll
            for (int ns = 0; ns < 8; ns++) {
                int n = n0 + ns * 8 + gr;
                bh[ns][0] = Bh[n * SW + kk + tc];
                bh[ns][1] = Bh[n * SW + kk + tc + 4];
                bl[ns][0] = Bl[n * SW + kk + tc];
                bl[ns][1] = Bl[n * SW + kk + tc + 4];
            }
            #pragma unroll
            for (int ms = 0; ms < 2; ms++)
                #pragma unroll
                for (int ns = 0; ns < 8; ns++) {
                    MMA_BF16(acc[ms][ns], ah[ms], bh[ns]);
                    MMA_BF16(acc[ms][ns], ah[ms], bl[ns]);
                    MMA_BF16(acc[ms][ns], al[ms], bh[ns]);
                }
        }
    }
    __syncthreads();   // MMAs done; whole smem reusable

    // ---- D (regs) -> SMEM col-major [col][row], stride SD ----
    float* Dcol = reinterpret_cast<float*>(smem);           // 128*132*4 = 67584 B
    float* pooled = reinterpret_cast<float*>(smem + 69632); // NIMG*128 floats
    #pragma unroll
    for (int ms = 0; ms < 2; ms++) {
        int r = m0 + ms * 16 + gr;
        #pragma unroll
        for (int ns = 0; ns < 8; ns++) {
            int c = n0 + ns * 8 + 2 * tc;
            Dcol[c * SD + r]           = acc[ms][ns][0];
            Dcol[(c + 1) * SD + r]     = acc[ms][ns][1];
            Dcol[c * SD + r + 8]       = acc[ms][ns][2];
            Dcol[(c + 1) * SD + r + 8] = acc[ms][ns][3];
        }
    }
    __syncthreads();

    // ---- Masked max over objects per (image, col) ----
    for (int u = tid; u < NIMG * 128; u += 256) {
        int j = u >> 7, c = u & 127;
        int lim = (j < ng) ? img_l[gi * NIMG + j] : 0;
        float m = NEG_BIG;
        const float* col = Dcol + c * SD + j * O;
        for (int r = 0; r < lim; r++) m = fmaxf(m, col[r]);
        pooled[u] = m;
    }
    __syncthreads();

    // ---- Per-(image, caption) word sums -> global scores ----
    if (tid < NIMG * NCAP) {
        int j = tid / NCAP, ci = tid % NCAP;
        if (j < ng) {
            float s = 0.0f;
            #pragma unroll
            for (int w = 0; w < W; w++) s += pooled[j * 128 + ci * CSLOT + w];
            int i = gi * NIMG + j, c = cg * NCAP + ci;
            float r = s / (float)cap_l[c];
            if (SLOT == 0) g_s1[i * B + c] = r;
            else           g_s2[i * B + c] = g_s1[i * B + c] + r;
        }
    }
}

// ---------------------------------------------------------------------------
// Hinge loss over B x B total scores (g_s2). Deterministic.
// ---------------------------------------------------------------------------
__global__ void loss_kernel(float* __restrict__ out, int B)
{
    __shared__ float red[128];
    const int t = threadIdx.x;
    const float dt = g_s2[t * B + t];
    float m1 = 0.0f, m2 = 0.0f;
    for (int k = 0; k < B; k++) {
        if (k == t) continue;
        m1 = fmaxf(m1, MARGIN + g_s2[t * B + k] - dt);
        m2 = fmaxf(m2, MARGIN + g_s2[k * B + t] - dt);
    }
    red[t] = m1 + m2;
    __syncthreads();
    for (int s = 64; s > 0; s >>= 1) {
        if (t < s && t + s < B) red[t] += red[t + s];
        __syncthreads();
    }
    if (t == 0) out[0] = red[0];
}

// ---------------------------------------------------------------------------
// Inputs (metadata order):
//  0 im (B,36,128) f32 | 1 im_l (B) i32 | 2 s (B,50,128) f32 | 3 s_l (B) i32
//  4 pred (B,25,128)   | 5 pred_l       | 6/7 unused | 8 c_r_pred (B,30,128) | 9 c_r_l
// Output: scalar f32.
// ---------------------------------------------------------------------------
extern "C" void kernel_launch(void* const* d_in, const int* in_sizes, int n_in,
                              void* d_out, int out_size)
{
    const float* im     = (const float*)d_in[0];
    const int*   im_l   = (const int*)  d_in[1];
    const float* s      = (const float*)d_in[2];
    const int*   s_l    = (const int*)  d_in[3];
    const float* pred   = (const float*)d_in[4];
    const int*   pred_l = (const int*)  d_in[5];
    const float* crp    = (const float*)d_in[8];
    const int*   crl    = (const int*)  d_in[9];

    const int B = in_sizes[1];   // 128

    cudaFuncSetAttribute(score_tc<36, 50, 3, 2, 64, 0>,
                         cudaFuncAttributeMaxDynamicSharedMemorySize, SMEM_TOTAL);
    cudaFuncSetAttribute(score_tc<25, 30, 5, 4, 32, 1>,
                         cudaFuncAttributeMaxDynamicSharedMemorySize, SMEM_TOTAL);

    // Term 1: 3 images x 2 captions per CTA -> grid (64, 43)
    score_tc<36, 50, 3, 2, 64, 0><<<dim3(B / 2, (B + 2) / 3), 256, SMEM_TOTAL>>>(
        im, im_l, s, s_l, B);

    // Term 2: 5 images x 4 captions per CTA -> grid (32, 26)
    score_tc<25, 30, 5, 4, 32, 1><<<dim3(B / 4, (B + 4) / 5), 256, SMEM_TOTAL>>>(
        pred, pred_l, crp, crl, B);

    loss_kernel<<<1, 128>>>((float*)d_out, B);
}

// round 7
// speedup vs baseline: 3.5809x; 1.0098x over previous
#include <cuda_runtime.h>
#include <cstdint>

#define MARGIN 0.2f
#define NEG_BIG (-3.0e38f)

// Scratch (device globals; no allocation allowed).
__device__ float g_s1[128 * 128];   // term-1 scores
__device__ float g_s2[128 * 128];   // TOTAL scores (term1 + term2)

// Preprocessed bf16 hi/lo planes: per row 64 words (128 elems as bf16x2).
// Rows: im 128*36=4608 | s 128*50=6400 | pred 128*25=3200 | crp 128*30=3840
__device__ uint32_t g_im_hi[4608 * 64],  g_im_lo[4608 * 64];
__device__ uint32_t g_s_hi [6400 * 64],  g_s_lo [6400 * 64];
__device__ uint32_t g_pr_hi[3200 * 64],  g_pr_lo[3200 * 64];
__device__ uint32_t g_cr_hi[3840 * 64],  g_cr_lo[3840 * 64];

__device__ __forceinline__ float bf16_hi(float a) {
    uint16_t u;
    asm("cvt.rn.bf16.f32 %0, %1;" : "=h"(u) : "f"(a));
    return __uint_as_float(((uint32_t)u) << 16);
}
__device__ __forceinline__ uint32_t pack_bf16x2(float a, float b) {
    uint32_t r;
    asm("cvt.rn.bf16x2.f32 %0, %1, %2;" : "=r"(r) : "f"(b), "f"(a));
    return r;
}

// m16n8k16 bf16 MMA, fp32 accumulate (sm_80+ path; compiles for base sm_103)
#define MMA_BF16(d, a, b) \
    asm volatile("mma.sync.aligned.m16n8k16.row.col.f32.bf16.bf16.f32 " \
        "{%0,%1,%2,%3}, {%4,%5,%6,%7}, {%8,%9}, {%0,%1,%2,%3};" \
        : "+f"((d)[0]), "+f"((d)[1]), "+f"((d)[2]), "+f"((d)[3]) \
        : "r"((a)[0]), "r"((a)[1]), "r"((a)[2]), "r"((a)[3]), \
          "r"((b)[0]), "r"((b)[1]))

// ---- Preprocess: fp32 -> hi/lo bf16x2 planes, all 4 tensors in one kernel.
static constexpr int NQ_IM = 4608 * 32;   // float4 count
static constexpr int NQ_S  = 6400 * 32;
static constexpr int NQ_PR = 3200 * 32;
static constexpr int NQ_CR = 3840 * 32;
static constexpr int NQ_TOTAL = NQ_IM + NQ_S + NQ_PR + NQ_CR;   // 577536

__global__ __launch_bounds__(256)
void preprocess(const float* __restrict__ im, const float* __restrict__ s,
                const float* __restrict__ pr, const float* __restrict__ cr)
{
    int idx = blockIdx.x * 256 + threadIdx.x;
    if (idx >= NQ_TOTAL) return;
    const float4* src;
    uint2 *hi, *lo;
    int local = idx;
    if (idx < NQ_IM) {
        src = (const float4*)im; hi = (uint2*)g_im_hi; lo = (uint2*)g_im_lo;
    } else if (idx < NQ_IM + NQ_S) {
        local -= NQ_IM;
        src = (const float4*)s;  hi = (uint2*)g_s_hi;  lo = (uint2*)g_s_lo;
    } else if (idx < NQ_IM + NQ_S + NQ_PR) {
        local -= NQ_IM + NQ_S;
        src = (const float4*)pr; hi = (uint2*)g_pr_hi; lo = (uint2*)g_pr_lo;
    } else {
        local -= NQ_IM + NQ_S + NQ_PR;
        src = (const float4*)cr; hi = (uint2*)g_cr_hi; lo = (uint2*)g_cr_lo;
    }
    float4 v = src[local];
    float hx = bf16_hi(v.x), hy = bf16_hi(v.y);
    float hz = bf16_hi(v.z), hw = bf16_hi(v.w);
    uint2 hwd, lwd;
    hwd.x = (__float_as_uint(hy) & 0xFFFF0000u) | (__float_as_uint(hx) >> 16);
    hwd.y = (__float_as_uint(hw) & 0xFFFF0000u) | (__float_as_uint(hz) >> 16);
    lwd.x = pack_bf16x2(v.x - hx, v.y - hy);
    lwd.y = pack_bf16x2(v.z - hz, v.w - hw);
    hi[local] = hwd;
    lo[local] = lwd;
}

// ---- SMEM: K chunked by 64 (32 words/row). Row stride 36 words
// (36 mod 32 == 4) -> fragment LDS bank = 4*gr + tc covers all 32 banks.
static constexpr int KC = 64;                       // K chunk (elements)
static constexpr int SW = 36;                       // row stride (words)
static constexpr int OFF_A_HI = 0;                  // 128*36*4 = 18432 B
static constexpr int OFF_A_LO = 18432;
static constexpr int OFF_B_HI = 36864;
static constexpr int OFF_B_LO = 55296;
static constexpr int SMEM_TOTAL = 73728;            // 72 KB -> 2 CTAs/SM
static constexpr int SD = 131;  // epilogue Dcol stride: odd -> conflict-free reads

// ---------------------------------------------------------------------------
// score_tc<O, W, NIMG, NCAP, CSLOT, SLOT>
// CTA: M=128 rows = NIMG images x O objects (zero-padded),
//      N=128 cols = NCAP captions x CSLOT word slots (zero-padded).
// Operands pre-split to bf16 hi/lo planes; staging is pure uint4 copy.
// 3-pass bf16 split: D = Ahi*Bhi + Ahi*Blo + Alo*Bhi.
// ---------------------------------------------------------------------------
template<int O, int W, int NIMG, int NCAP, int CSLOT, int SLOT>
__global__ __launch_bounds__(256, 2)
void score_tc(const uint32_t* __restrict__ Ahi_g,
              const uint32_t* __restrict__ Alo_g,
              const uint32_t* __restrict__ Bhi_g,
              const uint32_t* __restrict__ Blo_g,
              const int* __restrict__ img_l,
              const int* __restrict__ cap_l,
              int B)
{
    extern __shared__ char smem[];
    uint32_t* Ah = reinterpret_cast<uint32_t*>(smem + OFF_A_HI);
    uint32_t* Al = reinterpret_cast<uint32_t*>(smem + OFF_A_LO);
    uint32_t* Bh = reinterpret_cast<uint32_t*>(smem + OFF_B_HI);
    uint32_t* Bl = reinterpret_cast<uint32_t*>(smem + OFF_B_LO);

    const int tid  = threadIdx.x;
    const int wid  = tid >> 5;
    const int lane = tid & 31;
    const int gr   = lane >> 2;
    const int tc   = lane & 3;

    const int gi = blockIdx.y;
    const int cg = blockIdx.x;
    const int ng = min(NIMG, B - gi * NIMG);
    const int arows = ng * O;
    const int gbase = gi * NIMG * O;            // global A row base

    const int wm = wid & 3, wn = wid >> 2;
    const int m0 = wm * 32, n0 = wn * 64;

    float acc[2][8][4];
    #pragma unroll
    for (int ms = 0; ms < 2; ms++)
        #pragma unroll
        for (int ns = 0; ns < 8; ns++)
            #pragma unroll
            for (int j = 0; j < 4; j++) acc[ms][ns][j] = 0.0f;

    const uint4* Ahi4 = reinterpret_cast<const uint4*>(Ahi_g);
    const uint4* Alo4 = reinterpret_cast<const uint4*>(Alo_g);
    const uint4* Bhi4 = reinterpret_cast<const uint4*>(Bhi_g);
    const uint4* Blo4 = reinterpret_cast<const uint4*>(Blo_g);
    const uint4 zero4 = make_uint4(0u, 0u, 0u, 0u);

    #pragma unroll 1
    for (int chunk = 0; chunk < 2; chunk++) {
        __syncthreads();   // previous chunk consumed

        // ---- Stage A chunk: pure copy (row = 8 uint4 of 32 words) ----
        #pragma unroll
        for (int u = tid; u < 128 * 8; u += 256) {
            int r = u >> 3, q = u & 7;
            uint4 h = zero4, l = zero4;
            if (r < arows) {
                int gidx = (gbase + r) * 16 + chunk * 8 + q;
                h = Ahi4[gidx]; l = Alo4[gidx];
            }
            int wi = r * SW + q * 4;
            *reinterpret_cast<uint4*>(Ah + wi) = h;
            *reinterpret_cast<uint4*>(Al + wi) = l;
        }
        // ---- Stage B chunk: slot-padded copy ----
        #pragma unroll
        for (int u = tid; u < 128 * 8; u += 256) {
            int n = u >> 3, q = u & 7;
            int ci = n / CSLOT, w = n % CSLOT;
            uint4 h = zero4, l = zero4;
            if (w < W) {
                int gidx = ((cg * NCAP + ci) * W + w) * 16 + chunk * 8 + q;
                h = Bhi4[gidx]; l = Blo4[gidx];
            }
            int wi = n * SW + q * 4;
            *reinterpret_cast<uint4*>(Bh + wi) = h;
            *reinterpret_cast<uint4*>(Bl + wi) = l;
        }
        __syncthreads();

        // ---- 4 k-steps of 16 per chunk ----
        #pragma unroll
        for (int kk = 0; kk < KC / 2; kk += 8) {
            uint32_t ah[2][4], al[2][4];
            #pragma unroll
            for (int ms = 0; ms < 2; ms++) {
                int r = m0 + ms * 16 + gr;
                ah[ms][0] = Ah[r * SW + kk + tc];
                ah[ms][1] = Ah[(r + 8) * SW + kk + tc];
                ah[ms][2] = Ah[r * SW + kk + tc + 4];
                ah[ms][3] = Ah[(r + 8) * SW + kk + tc + 4];
                al[ms][0] = Al[r * SW + kk + tc];
                al[ms][1] = Al[(r + 8) * SW + kk + tc];
                al[ms][2] = Al[r * SW + kk + tc + 4];
                al[ms][3] = Al[(r + 8) * SW + kk + tc + 4];
            }
            uint32_t bh[8][2], bl[8][2];
            #pragma unroll
            for (int ns = 0; ns < 8; ns++) {
                int n = n0 + ns * 8 + gr;
                bh[ns][0] = Bh[n * SW + kk + tc];
                bh[ns][1] = Bh[n * SW + kk + tc + 4];
                bl[ns][0] = Bl[n * SW + kk + tc];
                bl[ns][1] = Bl[n * SW + kk + tc + 4];
            }
            #pragma unroll
            for (int ms = 0; ms < 2; ms++)
                #pragma unroll
                for (int ns = 0; ns < 8; ns++) {
                    MMA_BF16(acc[ms][ns], ah[ms], bh[ns]);
                    MMA_BF16(acc[ms][ns], ah[ms], bl[ns]);
                    MMA_BF16(acc[ms][ns], al[ms], bh[ns]);
                }
        }
    }
    __syncthreads();   // MMAs done; whole smem reusable

    // ---- D (regs) -> SMEM col-major [col][row], stride SD=131 ----
    float* Dcol = reinterpret_cast<float*>(smem);           // 128*131*4 = 67072 B
    float* pooled = reinterpret_cast<float*>(smem + 67072); // NIMG*128 floats
    #pragma unroll
    for (int ms = 0; ms < 2; ms++) {
        int r = m0 + ms * 16 + gr;
        #pragma unroll
        for (int ns = 0; ns < 8; ns++) {
            int c = n0 + ns * 8 + 2 * tc;
            Dcol[c * SD + r]           = acc[ms][ns][0];
            Dcol[(c + 1) * SD + r]     = acc[ms][ns][1];
            Dcol[c * SD + r + 8]       = acc[ms][ns][2];
            Dcol[(c + 1) * SD + r + 8] = acc[ms][ns][3];
        }
    }
    __syncthreads();

    // ---- Masked max over objects per (image, col); stride-131 reads are
    // conflict-free across consecutive-c lanes ----
    for (int u = tid; u < NIMG * 128; u += 256) {
        int j = u >> 7, c = u & 127;
        int lim = (j < ng) ? img_l[gi * NIMG + j] : 0;
        float m = NEG_BIG;
        const float* col = Dcol + c * SD + j * O;
        for (int r = 0; r < lim; r++) m = fmaxf(m, col[r]);
        pooled[u] = m;
    }
    __syncthreads();

    // ---- Per-(image, caption) word sums -> global scores ----
    if (tid < NIMG * NCAP) {
        int j = tid / NCAP, ci = tid % NCAP;
        if (j < ng) {
            float s = 0.0f;
            #pragma unroll
            for (int w = 0; w < W; w++) s += pooled[j * 128 + ci * CSLOT + w];
            int i = gi * NIMG + j, c = cg * NCAP + ci;
            float r = s / (float)cap_l[c];
            if (SLOT == 0) g_s1[i * B + c] = r;
            else           g_s2[i * B + c] = g_s1[i * B + c] + r;
        }
    }
}

// ---------------------------------------------------------------------------
// Hinge loss over B x B total scores (g_s2). Deterministic.
// ---------------------------------------------------------------------------
__global__ void loss_kernel(float* __restrict__ out, int B)
{
    __shared__ float red[128];
    const int t = threadIdx.x;
    const float dt = g_s2[t * B + t];
    float m1 = 0.0f, m2 = 0.0f;
    for (int k = 0; k < B; k++) {
        if (k == t) continue;
        m1 = fmaxf(m1, MARGIN + g_s2[t * B + k] - dt);
        m2 = fmaxf(m2, MARGIN + g_s2[k * B + t] - dt);
    }
    red[t] = m1 + m2;
    __syncthreads();
    for (int s = 64; s > 0; s >>= 1) {
        if (t < s && t + s < B) red[t] += red[t + s];
        __syncthreads();
    }
    if (t == 0) out[0] = red[0];
}

// ---------------------------------------------------------------------------
// Inputs (metadata order):
//  0 im (B,36,128) f32 | 1 im_l (B) i32 | 2 s (B,50,128) f32 | 3 s_l (B) i32
//  4 pred (B,25,128)   | 5 pred_l       | 6/7 unused | 8 c_r_pred (B,30,128) | 9 c_r_l
// Output: scalar f32.
// ---------------------------------------------------------------------------
extern "C" void kernel_launch(void* const* d_in, const int* in_sizes, int n_in,
                              void* d_out, int out_size)
{
    const float* im     = (const float*)d_in[0];
    const int*   im_l   = (const int*)  d_in[1];
    const float* s      = (const float*)d_in[2];
    const int*   s_l    = (const int*)  d_in[3];
    const float* pred   = (const float*)d_in[4];
    const int*   pred_l = (const int*)  d_in[5];
    const float* crp    = (const float*)d_in[8];
    const int*   crl    = (const int*)  d_in[9];

    const int B = in_sizes[1];   // 128

    static uint32_t *p_im_hi = nullptr, *p_im_lo, *p_s_hi, *p_s_lo,
                    *p_pr_hi, *p_pr_lo, *p_cr_hi, *p_cr_lo;
    if (!p_im_hi) {
        cudaGetSymbolAddress((void**)&p_im_hi, g_im_hi);
        cudaGetSymbolAddress((void**)&p_im_lo, g_im_lo);
        cudaGetSymbolAddress((void**)&p_s_hi,  g_s_hi);
        cudaGetSymbolAddress((void**)&p_s_lo,  g_s_lo);
        cudaGetSymbolAddress((void**)&p_pr_hi, g_pr_hi);
        cudaGetSymbolAddress((void**)&p_pr_lo, g_pr_lo);
        cudaGetSymbolAddress((void**)&p_cr_hi, g_cr_hi);
        cudaGetSymbolAddress((void**)&p_cr_lo, g_cr_lo);
        cudaFuncSetAttribute(score_tc<36, 50, 3, 2, 64, 0>,
                             cudaFuncAttributeMaxDynamicSharedMemorySize, SMEM_TOTAL);
        cudaFuncSetAttribute(score_tc<25, 30, 5, 4, 32, 1>,
                             cudaFuncAttributeMaxDynamicSharedMemorySize, SMEM_TOTAL);
    }

    preprocess<<<(NQ_TOTAL + 255) / 256, 256>>>(im, s, pred, crp);

    // Term 1: 3 images x 2 captions per CTA -> grid (64, 43)
    score_tc<36, 50, 3, 2, 64, 0><<<dim3(B / 2, (B + 2) / 3), 256, SMEM_TOTAL>>>(
        p_im_hi, p_im_lo, p_s_hi, p_s_lo, im_l, s_l, B);

    // Term 2: 5 images x 4 captions per CTA -> grid (32, 26)
    score_tc<25, 30, 5, 4, 32, 1><<<dim3(B / 4, (B + 4) / 5), 256, SMEM_TOTAL>>>(
        p_pr_hi, p_pr_lo, p_cr_hi, p_cr_lo, pred_l, crl, B);

    loss_kernel<<<1, 128>>>((float*)d_out, B);
}